// round 13
// baseline (speedup 1.0000x reference)
#include <cuda_runtime.h>
#include <cuda_fp16.h>

// ---------------- problem constants ----------------
#define Dd 1024
#define Hh 4096
#define Oo 1024
#define Ee 8
#define Tt 4096
#define A2 (2 * Tt)
#define HR (A2 + Tt)       // unified hidden rows: experts [0,A2), shared [A2, A2+Tt)

// GEMM tiling: CTA 128x128, 4 warps of 64x64, k-chunk 64 (128 B rows), 2 CTAs/SM, persistent
#define BMt 128
#define BNt 128
#define BKb 64
#define NTHR 128
#define OP_A 16384          // 128 rows * 128 B
#define OP_B 16384          // 128 rows * 128 B
#define STAGE_B (2 * OP_A + OP_B)   // 49152: A-hi, A-lo, B
#define SM_OFF 1024
#define SMEM_TOT (SM_OFF + 2 * STAGE_B)   // 99328 -> 2 CTAs/SM

// ---------------- scratch ----------------
__device__ __half g_nh[(size_t)Tt * Dd],  g_nl[(size_t)Tt * Dd];
__device__ __half g_hh[(size_t)HR * Hh],  g_hl[(size_t)HR * Hh];   // unified hidden hi/lo
__device__ __half g_sw1h[(size_t)Hh * Dd];                          // [N=H, K=D] fp16
__device__ __half g_sw2h[(size_t)Oo * Hh];
__device__ __half g_ew1h[(size_t)Ee * Hh * Dd];
__device__ __half g_ew2h[(size_t)Ee * Oo * Hh];
__device__ int   g_cnt[Ee], g_tok[Ee * Tt];
__device__ float g_wt[Ee * Tt];

// ---------------- ptx helpers ----------------
__device__ __forceinline__ unsigned smem_u32(const void* p) {
    unsigned a;
    asm("{ .reg .u64 t; cvta.to.shared.u64 t, %1; cvt.u32.u64 %0, t; }" : "=r"(a) : "l"(p));
    return a;
}
#define CP16(dst, src) asm volatile("cp.async.cg.shared.global [%0], [%1], 16;" :: "r"(dst), "l"(src) : "memory")
#define CP_COMMIT() asm volatile("cp.async.commit_group;" ::: "memory")
#define CP_WAIT0()  asm volatile("cp.async.wait_group 0;" ::: "memory")

#define LDSM4(r0, r1, r2, r3, addr) \
    asm volatile("ldmatrix.sync.aligned.m8n8.x4.shared.b16 {%0,%1,%2,%3}, [%4];" \
        : "=r"(r0), "=r"(r1), "=r"(r2), "=r"(r3) : "r"(addr))

#define MMAF16(d, a0, a1, a2, a3, b0v, b1v) \
    asm volatile("mma.sync.aligned.m16n8k16.row.col.f32.f16.f16.f32 " \
        "{%0,%1,%2,%3}, {%4,%5,%6,%7}, {%8,%9}, {%0,%1,%2,%3};" \
        : "+f"((d)[0]), "+f"((d)[1]), "+f"((d)[2]), "+f"((d)[3]) \
        : "r"(a0), "r"(a1), "r"(a2), "r"(a3), "r"(b0v), "r"(b1v))

// swizzled byte offset within one operand tile (128 B rows, 8 x 16B chunks)
__device__ __forceinline__ unsigned swz(int row, int chunk) {
    return (unsigned)(row * 128 + ((chunk ^ (row & 7)) << 4));
}
__device__ __forceinline__ unsigned pack2h(float v0, float v1) {
    __half h0 = __float2half(v0), h1 = __float2half(v1);
    return ((unsigned)__half_as_ushort(h1) << 16) | __half_as_ushort(h0);
}

// ---------------- small kernels ----------------
__global__ void __launch_bounds__(256) zero_out_kernel(float4* out) {
    out[blockIdx.x * 256 + threadIdx.x] = make_float4(0.f, 0.f, 0.f, 0.f);
}

// weight transpose + fp16 convert: W[K,N] fp32 -> Wh[N,K] fp16 (optionally zero cnt)
__global__ void __launch_bounds__(256) splitT_kernel(
    const float* __restrict__ W, __half* __restrict__ hiT, int K, int N, int zeroCnt)
{
    if (zeroCnt && blockIdx.x == 0 && blockIdx.y == 0 && blockIdx.z == 0 && threadIdx.x < Ee)
        g_cnt[threadIdx.x] = 0;
    const int e = blockIdx.z;
    W   += (size_t)e * K * N;
    hiT += (size_t)e * N * K;
    __shared__ float tile[32][33];
    const int k0 = blockIdx.y * 32, n0 = blockIdx.x * 32;
    {
        const int tx = threadIdx.x & 31, ty = threadIdx.x >> 5;
        #pragma unroll
        for (int i = 0; i < 4; i++)
            tile[ty + 8 * i][tx] = W[(size_t)(k0 + ty + 8 * i) * N + n0 + tx];
    }
    __syncthreads();
    const int tx2 = threadIdx.x & 15;
    const int ty2 = threadIdx.x >> 4;
    #pragma unroll
    for (int i = 0; i < 2; i++) {
        const int nl = ty2 + 16 * i;
        const int kl = tx2 * 2;
        size_t o = (size_t)(n0 + nl) * K + k0 + kl;
        *reinterpret_cast<unsigned*>(hiT + o) = pack2h(tile[kl][nl], tile[kl + 1][nl]);
    }
}

// RMSNorm + router + top-2 scatter; emits hi/lo fp16 normed activations
__global__ void __launch_bounds__(256) norm_router_kernel(
    const float* __restrict__ x, const float* __restrict__ nw, const float* __restrict__ rw)
{
    const int t = blockIdx.x;
    const float* xr = x + (size_t)t * Dd;
    __shared__ float sx[Dd];
    __shared__ float red[8];
    __shared__ float s_rstd;
    __shared__ float slog[Ee];

    float ss = 0.f;
    for (int d = threadIdx.x; d < Dd; d += 256) {
        float v = xr[d]; sx[d] = v; ss += v * v;
    }
    #pragma unroll
    for (int o = 16; o; o >>= 1) ss += __shfl_xor_sync(0xFFFFFFFFu, ss, o);
    if ((threadIdx.x & 31) == 0) red[threadIdx.x >> 5] = ss;
    __syncthreads();
    if (threadIdx.x == 0) {
        float s = 0.f;
        #pragma unroll
        for (int i = 0; i < 8; i++) s += red[i];
        s_rstd = rsqrtf(s / (float)Dd + 1e-8f);
    }
    __syncthreads();
    const float rstd = s_rstd;
    for (int d = threadIdx.x; d < Dd; d += 256) {
        float v = sx[d] * rstd * nw[d];
        sx[d] = v;
        __half h = __float2half(v);
        g_nh[(size_t)t * Dd + d] = h;
        g_nl[(size_t)t * Dd + d] = __float2half(v - __half2float(h));
    }
    __syncthreads();

    const int w = threadIdx.x >> 5, lane = threadIdx.x & 31;
    if (w < Ee) {
        const float* rwr = rw + (size_t)w * Dd;
        float acc = 0.f;
        for (int d = lane; d < Dd; d += 32) acc += sx[d] * rwr[d];
        #pragma unroll
        for (int o = 16; o; o >>= 1) acc += __shfl_xor_sync(0xFFFFFFFFu, acc, o);
        if (lane == 0) slog[w] = acc;
    }
    __syncthreads();

    if (threadIdx.x == 0) {
        float p[Ee];
        #pragma unroll
        for (int e = 0; e < Ee; e++) p[e] = 1.f / (1.f + expf(-slog[e]));
        int i0 = 0;
        #pragma unroll
        for (int e = 1; e < Ee; e++) if (p[e] > p[i0]) i0 = e;
        int i1 = (i0 == 0) ? 1 : 0;
        #pragma unroll
        for (int e = 0; e < Ee; e++) { if (e == i0) continue; if (p[e] > p[i1]) i1 = e; }
        float s0 = p[i0], s1 = p[i1];
        float inv = 1.f / (s0 + s1 + 1e-6f);
        int a = atomicAdd(&g_cnt[i0], 1);
        g_tok[i0 * Tt + a] = t; g_wt[i0 * Tt + a] = s0 * inv;
        int b = atomicAdd(&g_cnt[i1], 1);
        g_tok[i1 * Tt + b] = t; g_wt[i1 * Tt + b] = s1 * inv;
    }
}

// ---------------- pooled persistent HMMA fp16 2-term GEMM ----------------
// Persistent CTAs grid-stride over flattened tiles (e, my, nx); empty expert
// tiles skipped. A = (Ah + Al) fp16 pair, W = single fp16; 2 MMAs per tile-k.
// EPI 1: relu + fp16 hi/lo re-split into unified hidden at row offE+m.
// EPI 2: atomicAdd(out[tgt], wv*(acc+bias)).
template<int EPI>
__global__ void __launch_bounds__(NTHR, 2) mma_gemm(
    const __half* __restrict__ Ah, const __half* __restrict__ Al,
    const __half* __restrict__ eW, const __half* __restrict__ sW,
    const float* __restrict__ eBias, const float* __restrict__ sBias,
    float* __restrict__ Cf, __half* __restrict__ Ch, __half* __restrict__ Cl,
    int N, int K, int gx, int gy,
    const int* __restrict__ cnts,
    const int* __restrict__ tok, const float* __restrict__ wts)
{
    extern __shared__ char smem[];
    int* rowIdx = (int*)smem;               // 128 ints at [0,512)
    const unsigned sb = smem_u32(smem);
    const int tid = threadIdx.x, wid = tid >> 5, lane = tid & 31;

    const int warpM = (wid >> 1) * 64;
    const int warpN = (wid & 1) * 64;
    const int arow  = ((lane >> 3) & 1) * 8 + (lane & 7);
    const int ahalf = lane >> 4;
    const int brow  = (lane & 7) + ((lane >> 4) & 1) * 8;
    const int bhalf = (lane >> 3) & 1;
    const int qr = lane >> 2, qc = (lane & 3) * 2;
    const int nChunks = K >> 6;
    const int nTiles = (Ee + 1) * gy * gx;

    // per-thread copy of counts (uniform across CTA)
    int cn[Ee];
    #pragma unroll
    for (int i = 0; i < Ee; i++) cn[i] = cnts[i];

    for (int tile = blockIdx.x; tile < nTiles; tile += gridDim.x) {
        const int e  = tile / (gy * gx);
        const int r1 = tile - e * gy * gx;
        const int my = r1 / gx;
        const int nx = r1 - my * gx;
        const bool isShared = (e == Ee);

        int offE = 0;
        #pragma unroll
        for (int i = 0; i < Ee; i++) if (i < e) offE += cn[i];
        const int M = isShared ? Tt : cn[e];
        const int mBase = my * BMt;
        if (mBase >= M) continue;
        const int nBase = nx * BNt;
        const int tokB = e * Tt;

        if (tid < BMt) {
            int m = mBase + tid; if (m > M - 1) m = M - 1;
            int r;
            if (EPI == 1) r = isShared ? m : tok[tokB + m];
            else          r = offE + m;
            rowIdx[tid] = r;
        }
        __syncthreads();

        const __half* We = (isShared ? sW : eW + (size_t)e * N * K) + (size_t)nBase * K;
        const float* be = (isShared ? sBias : eBias + (size_t)e * N);

        float acc[4][8][4];
        #pragma unroll
        for (int i = 0; i < 4; i++)
            #pragma unroll
            for (int j = 0; j < 8; j++)
                #pragma unroll
                for (int q = 0; q < 4; q++) acc[i][j][q] = 0.f;

        auto load_chunk = [&](int chunk, int stage) {
            const int k0 = chunk * BKb;
            const unsigned st = sb + SM_OFF + stage * STAGE_B;
            #pragma unroll
            for (int i = 0; i < 8; i++) {             // A: 1024 x 16B per plane
                int idx = tid + i * NTHR;
                int r = idx >> 3, c = idx & 7;
                unsigned o = swz(r, c);
                size_t aoff = (size_t)rowIdx[r] * K + k0 + c * 8;
                CP16(st + o,        Ah + aoff);
                CP16(st + OP_A + o, Al + aoff);
            }
            #pragma unroll
            for (int i = 0; i < 8; i++) {             // B: 1024 x 16B
                int idx = tid + i * NTHR;
                int r = idx >> 3, c = idx & 7;
                unsigned o = swz(r, c);
                size_t boff = (size_t)r * K + k0 + c * 8;
                CP16(st + 2 * OP_A + o, We + boff);
            }
        };

        auto compute = [&](int stage) {
            const unsigned st = sb + SM_OFF + stage * STAGE_B;
            #pragma unroll
            for (int ks = 0; ks < 4; ks++) {
                unsigned ah[4][4], bh[4][4];
                #pragma unroll
                for (int mf = 0; mf < 4; mf++) {
                    int R = warpM + mf * 16 + arow;
                    unsigned o = swz(R, ks * 2 + ahalf);
                    LDSM4(ah[mf][0], ah[mf][1], ah[mf][2], ah[mf][3], st + o);
                }
                #pragma unroll
                for (int g = 0; g < 4; g++) {
                    int Rn = warpN + g * 16 + brow;
                    unsigned o = swz(Rn, ks * 2 + bhalf);
                    LDSM4(bh[g][0], bh[g][1], bh[g][2], bh[g][3], st + 2 * OP_A + o);
                }
                #pragma unroll
                for (int g = 0; g < 4; g++)
                    #pragma unroll
                    for (int mf = 0; mf < 4; mf++) {
                        MMAF16(acc[mf][2 * g],     ah[mf][0], ah[mf][1], ah[mf][2], ah[mf][3], bh[g][0], bh[g][1]);
                        MMAF16(acc[mf][2 * g + 1], ah[mf][0], ah[mf][1], ah[mf][2], ah[mf][3], bh[g][2], bh[g][3]);
                    }
                unsigned al[4][4];
                #pragma unroll
                for (int mf = 0; mf < 4; mf++) {
                    int R = warpM + mf * 16 + arow;
                    unsigned o = swz(R, ks * 2 + ahalf);
                    LDSM4(al[mf][0], al[mf][1], al[mf][2], al[mf][3], st + OP_A + o);
                }
                #pragma unroll
                for (int g = 0; g < 4; g++)
                    #pragma unroll
                    for (int mf = 0; mf < 4; mf++) {
                        MMAF16(acc[mf][2 * g],     al[mf][0], al[mf][1], al[mf][2], al[mf][3], bh[g][0], bh[g][1]);
                        MMAF16(acc[mf][2 * g + 1], al[mf][0], al[mf][1], al[mf][2], al[mf][3], bh[g][2], bh[g][3]);
                    }
            }
        };

        load_chunk(0, 0); CP_COMMIT();
        for (int i = 0; i < nChunks; i++) {
            CP_WAIT0();
            __syncthreads();
            if (i + 1 < nChunks) { load_chunk(i + 1, (i + 1) & 1); CP_COMMIT(); }
            compute(i & 1);
        }

        // epilogue
        #pragma unroll
        for (int mf = 0; mf < 4; mf++) {
            #pragma unroll
            for (int h = 0; h < 2; h++) {
                const int m = mBase + warpM + mf * 16 + qr + h * 8;
                if (m >= M) continue;
                if (EPI == 2) {
                    const int   tt = isShared ? m : tok[tokB + m];
                    const float wv = isShared ? 1.f : wts[tokB + m];
                    float* orow = Cf + (size_t)tt * N;
                    #pragma unroll
                    for (int nf = 0; nf < 8; nf++) {
                        const int n = nBase + warpN + nf * 8 + qc;
                        atomicAdd(orow + n,     wv * (acc[mf][nf][h * 2 + 0] + be[n]));
                        atomicAdd(orow + n + 1, wv * (acc[mf][nf][h * 2 + 1] + be[n + 1]));
                    }
                } else {
                    __half* hrow = Ch + (size_t)(offE + m) * N;
                    __half* lrow = Cl + (size_t)(offE + m) * N;
                    #pragma unroll
                    for (int nf = 0; nf < 8; nf++) {
                        const int n = nBase + warpN + nf * 8 + qc;
                        float v0 = fmaxf(acc[mf][nf][h * 2 + 0] + be[n], 0.f);
                        float v1 = fmaxf(acc[mf][nf][h * 2 + 1] + be[n + 1], 0.f);
                        __half h0 = __float2half(v0), h1 = __float2half(v1);
                        float l0 = v0 - __half2float(h0), l1 = v1 - __half2float(h1);
                        *reinterpret_cast<unsigned*>(hrow + n) =
                            ((unsigned)__half_as_ushort(h1) << 16) | __half_as_ushort(h0);
                        *reinterpret_cast<unsigned*>(lrow + n) = pack2h(l0, l1);
                    }
                }
            }
        }
        __syncthreads();   // protect rowIdx before next tile overwrites it
    }
}

// ---------------- host launcher ----------------
extern "C" void kernel_launch(void* const* d_in, const int* in_sizes, int n_in,
                              void* d_out, int out_size)
{
    const float* hs  = (const float*)d_in[0];
    const float* nw  = (const float*)d_in[1];
    const float* rw  = (const float*)d_in[2];
    const float* sw1 = (const float*)d_in[3];
    const float* sb1 = (const float*)d_in[4];
    const float* sw2 = (const float*)d_in[5];
    const float* sb2 = (const float*)d_in[6];
    const float* ew1 = (const float*)d_in[7];
    const float* eb1 = (const float*)d_in[8];
    const float* ew2 = (const float*)d_in[9];
    const float* eb2 = (const float*)d_in[10];
    float* out = (float*)d_out;

    static int nPersist = 0;
    if (!nPersist) {
        cudaFuncSetAttribute(mma_gemm<1>, cudaFuncAttributeMaxDynamicSharedMemorySize, SMEM_TOT);
        cudaFuncSetAttribute(mma_gemm<2>, cudaFuncAttributeMaxDynamicSharedMemorySize, SMEM_TOT);
        int sm = 0;
        cudaDeviceGetAttribute(&sm, cudaDevAttrMultiProcessorCount, 0);
        nPersist = 2 * sm;
    }

    void *p;
    cudaGetSymbolAddress(&p, g_nh);   __half* nh  = (__half*)p;
    cudaGetSymbolAddress(&p, g_nl);   __half* nl  = (__half*)p;
    cudaGetSymbolAddress(&p, g_hh);   __half* hh  = (__half*)p;
    cudaGetSymbolAddress(&p, g_hl);   __half* hl  = (__half*)p;
    cudaGetSymbolAddress(&p, g_sw1h); __half* s1h = (__half*)p;
    cudaGetSymbolAddress(&p, g_sw2h); __half* s2h = (__half*)p;
    cudaGetSymbolAddress(&p, g_ew1h); __half* e1h = (__half*)p;
    cudaGetSymbolAddress(&p, g_ew2h); __half* e2h = (__half*)p;
    cudaGetSymbolAddress(&p, g_cnt);  int*   cnt  = (int*)p;
    cudaGetSymbolAddress(&p, g_tok);  int*   tokl = (int*)p;
    cudaGetSymbolAddress(&p, g_wt);   float* wtl  = (float*)p;

    const int gy = (Tt + BMt - 1) / BMt;   // 32

    // 1: sw1 convert (+ zero expert counters)
    splitT_kernel<<<dim3(Hh / 32, Dd / 32, 1), 256>>>(sw1, s1h, Dd, Hh, 1);
    // 2: ew1 convert
    splitT_kernel<<<dim3(Hh / 32, Dd / 32, Ee), 256>>>(ew1, e1h, Dd, Hh, 0);
    // 3: norm + router + scatter
    norm_router_kernel<<<Tt, 256>>>(hs, nw, rw);

    // 4: pooled persistent L1 (experts gather + shared)   <- ncu capture slot
    mma_gemm<1><<<nPersist, NTHR, SMEM_TOT>>>(
        nh, nl, e1h, s1h, eb1, sb1,
        nullptr, hh, hl, Hh, Dd, Hh / BNt, gy, cnt, tokl, wtl);

    // 5: zero output
    zero_out_kernel<<<(Tt * Oo / 4) / 256, 256>>>((float4*)out);
    // 6-7: layer-2 weight converts
    splitT_kernel<<<dim3(Oo / 32, Hh / 32, 1), 256>>>(sw2, s2h, Hh, Oo, 0);
    splitT_kernel<<<dim3(Oo / 32, Hh / 32, Ee), 256>>>(ew2, e2h, Hh, Oo, 0);

    // 8: pooled persistent L2 (scatter-atomic; shared weight 1.0)
    mma_gemm<2><<<nPersist, NTHR, SMEM_TOT>>>(
        hh, hl, e2h, s2h, eb2, sb2,
        out, nullptr, nullptr, Oo, Hh, Oo / BNt, gy, cnt, tokl, wtl);
}

// round 14
// speedup vs baseline: 1.3733x; 1.3733x over previous
#include <cuda_runtime.h>
#include <cuda_fp16.h>

// ---------------- problem constants ----------------
#define Dd 1024
#define Hh 4096
#define Oo 1024
#define Ee 8
#define Tt 4096
#define A2 (2 * Tt)
#define HR (A2 + Tt)       // unified hidden rows: experts [0,A2), shared [A2, A2+Tt)

// GEMM tiling: CTA 128x128, 4 warps of 64x64, k-chunk 64 (128 B rows), 2 CTAs/SM
#define BMt 128
#define BNt 128
#define BKb 64
#define NTHR 128
#define OP_T 16384          // one operand plane: 128 rows * 128 B
#define SM_OFF 1024

// ---------------- scratch ----------------
__device__ __half g_nh[(size_t)Tt * Dd],  g_nl[(size_t)Tt * Dd];
__device__ __half g_hh[(size_t)HR * Hh],  g_hl[(size_t)HR * Hh];   // unified hidden hi/lo
__device__ __half g_sw1h[(size_t)Hh * Dd];                          // [N=H, K=D] fp16
__device__ __half g_sw2h[(size_t)Oo * Hh];
__device__ __half g_ew1h[(size_t)Ee * Hh * Dd];
__device__ __half g_ew2h[(size_t)Ee * Oo * Hh];
__device__ int   g_cnt[Ee], g_tok[Ee * Tt];
__device__ float g_wt[Ee * Tt];

// ---------------- ptx helpers ----------------
__device__ __forceinline__ unsigned smem_u32(const void* p) {
    unsigned a;
    asm("{ .reg .u64 t; cvta.to.shared.u64 t, %1; cvt.u32.u64 %0, t; }" : "=r"(a) : "l"(p));
    return a;
}
#define CP16(dst, src) asm volatile("cp.async.cg.shared.global [%0], [%1], 16;" :: "r"(dst), "l"(src) : "memory")
#define CP_COMMIT() asm volatile("cp.async.commit_group;" ::: "memory")
#define CP_WAIT0()  asm volatile("cp.async.wait_group 0;" ::: "memory")

#define LDSM4(r0, r1, r2, r3, addr) \
    asm volatile("ldmatrix.sync.aligned.m8n8.x4.shared.b16 {%0,%1,%2,%3}, [%4];" \
        : "=r"(r0), "=r"(r1), "=r"(r2), "=r"(r3) : "r"(addr))

#define MMAF16(d, a0, a1, a2, a3, b0v, b1v) \
    asm volatile("mma.sync.aligned.m16n8k16.row.col.f32.f16.f16.f32 " \
        "{%0,%1,%2,%3}, {%4,%5,%6,%7}, {%8,%9}, {%0,%1,%2,%3};" \
        : "+f"((d)[0]), "+f"((d)[1]), "+f"((d)[2]), "+f"((d)[3]) \
        : "r"(a0), "r"(a1), "r"(a2), "r"(a3), "r"(b0v), "r"(b1v))

// swizzled byte offset within one operand tile (128 B rows, 8 x 16B chunks)
__device__ __forceinline__ unsigned swz(int row, int chunk) {
    return (unsigned)(row * 128 + ((chunk ^ (row & 7)) << 4));
}
__device__ __forceinline__ unsigned pack2h(float v0, float v1) {
    __half h0 = __float2half(v0), h1 = __float2half(v1);
    return ((unsigned)__half_as_ushort(h1) << 16) | __half_as_ushort(h0);
}

// ---------------- small kernels ----------------
__global__ void __launch_bounds__(256) zero_out_kernel(float4* out) {
    out[blockIdx.x * 256 + threadIdx.x] = make_float4(0.f, 0.f, 0.f, 0.f);
}

// weight transpose + fp16 convert: W[K,N] fp32 -> Wh[N,K] fp16 (optionally zero cnt)
__global__ void __launch_bounds__(256) splitT_kernel(
    const float* __restrict__ W, __half* __restrict__ hiT, int K, int N, int zeroCnt)
{
    if (zeroCnt && blockIdx.x == 0 && blockIdx.y == 0 && blockIdx.z == 0 && threadIdx.x < Ee)
        g_cnt[threadIdx.x] = 0;
    const int e = blockIdx.z;
    W   += (size_t)e * K * N;
    hiT += (size_t)e * N * K;
    __shared__ float tile[32][33];
    const int k0 = blockIdx.y * 32, n0 = blockIdx.x * 32;
    {
        const int tx = threadIdx.x & 31, ty = threadIdx.x >> 5;
        #pragma unroll
        for (int i = 0; i < 4; i++)
            tile[ty + 8 * i][tx] = W[(size_t)(k0 + ty + 8 * i) * N + n0 + tx];
    }
    __syncthreads();
    const int tx2 = threadIdx.x & 15;
    const int ty2 = threadIdx.x >> 4;
    #pragma unroll
    for (int i = 0; i < 2; i++) {
        const int nl = ty2 + 16 * i;
        const int kl = tx2 * 2;
        size_t o = (size_t)(n0 + nl) * K + k0 + kl;
        *reinterpret_cast<unsigned*>(hiT + o) = pack2h(tile[kl][nl], tile[kl + 1][nl]);
    }
}

// RMSNorm + router + top-2 scatter; emits hi/lo fp16 normed activations
__global__ void __launch_bounds__(256) norm_router_kernel(
    const float* __restrict__ x, const float* __restrict__ nw, const float* __restrict__ rw)
{
    const int t = blockIdx.x;
    const float* xr = x + (size_t)t * Dd;
    __shared__ float sx[Dd];
    __shared__ float red[8];
    __shared__ float s_rstd;
    __shared__ float slog[Ee];

    float ss = 0.f;
    for (int d = threadIdx.x; d < Dd; d += 256) {
        float v = xr[d]; sx[d] = v; ss += v * v;
    }
    #pragma unroll
    for (int o = 16; o; o >>= 1) ss += __shfl_xor_sync(0xFFFFFFFFu, ss, o);
    if ((threadIdx.x & 31) == 0) red[threadIdx.x >> 5] = ss;
    __syncthreads();
    if (threadIdx.x == 0) {
        float s = 0.f;
        #pragma unroll
        for (int i = 0; i < 8; i++) s += red[i];
        s_rstd = rsqrtf(s / (float)Dd + 1e-8f);
    }
    __syncthreads();
    const float rstd = s_rstd;
    for (int d = threadIdx.x; d < Dd; d += 256) {
        float v = sx[d] * rstd * nw[d];
        sx[d] = v;
        __half h = __float2half(v);
        g_nh[(size_t)t * Dd + d] = h;
        g_nl[(size_t)t * Dd + d] = __float2half(v - __half2float(h));
    }
    __syncthreads();

    const int w = threadIdx.x >> 5, lane = threadIdx.x & 31;
    if (w < Ee) {
        const float* rwr = rw + (size_t)w * Dd;
        float acc = 0.f;
        for (int d = lane; d < Dd; d += 32) acc += sx[d] * rwr[d];
        #pragma unroll
        for (int o = 16; o; o >>= 1) acc += __shfl_xor_sync(0xFFFFFFFFu, acc, o);
        if (lane == 0) slog[w] = acc;
    }
    __syncthreads();

    if (threadIdx.x == 0) {
        float p[Ee];
        #pragma unroll
        for (int e = 0; e < Ee; e++) p[e] = 1.f / (1.f + expf(-slog[e]));
        int i0 = 0;
        #pragma unroll
        for (int e = 1; e < Ee; e++) if (p[e] > p[i0]) i0 = e;
        int i1 = (i0 == 0) ? 1 : 0;
        #pragma unroll
        for (int e = 0; e < Ee; e++) { if (e == i0) continue; if (p[e] > p[i1]) i1 = e; }
        float s0 = p[i0], s1 = p[i1];
        float inv = 1.f / (s0 + s1 + 1e-6f);
        int a = atomicAdd(&g_cnt[i0], 1);
        g_tok[i0 * Tt + a] = t; g_wt[i0 * Tt + a] = s0 * inv;
        int b = atomicAdd(&g_cnt[i1], 1);
        g_tok[i1 * Tt + b] = t; g_wt[i1 * Tt + b] = s1 * inv;
    }
}

// ---------------- pooled HMMA fp16 GEMM (128x128 CTA, 4 warps, 2 CTAs/SM) ----------------
// EPI 1 (layer 1): A = (Ah + Al) 2-term split, 2 MMAs/tile-k; relu + hi/lo re-split out.
// EPI 2 (layer 2): A = single fp16 plane, 1 MMA/tile-k; weighted atomic scatter out.
template<int EPI>
__global__ void __launch_bounds__(NTHR, 2) mma_gemm(
    const __half* __restrict__ Ah, const __half* __restrict__ Al,
    const __half* __restrict__ eW, const __half* __restrict__ sW,
    const float* __restrict__ eBias, const float* __restrict__ sBias,
    float* __restrict__ Cf, __half* __restrict__ Ch, __half* __restrict__ Cl,
    int N, int K,
    const int* __restrict__ cnts,
    const int* __restrict__ tok, const float* __restrict__ wts)
{
    constexpr int APL = (EPI == 1) ? 2 : 1;            // A planes
    constexpr unsigned STB = (APL + 1) * OP_T;         // stage bytes

    const int e = blockIdx.z;
    const bool isShared = (e == Ee);

    extern __shared__ char smem[];
    int* rowIdx = (int*)smem;               // 128 ints at [0,512)
    int* sMeta  = (int*)(smem + 512);       // [0]=M, [1]=offE
    const unsigned sb = smem_u32(smem);
    const int tid = threadIdx.x, wid = tid >> 5, lane = tid & 31;

    if (tid == 0) {
        int run = 0;
        #pragma unroll
        for (int i = 0; i < Ee; i++) if (i < e) run += cnts[i];
        sMeta[1] = run;
        sMeta[0] = isShared ? Tt : cnts[e];
    }
    __syncthreads();
    const int M = sMeta[0], offE = sMeta[1];
    const int mBase = blockIdx.y * BMt;
    if (mBase >= M) return;
    const int nBase = blockIdx.x * BNt;
    const int tokB = e * Tt;

    if (tid < BMt) {
        int m = mBase + tid; if (m > M - 1) m = M - 1;
        int r;
        if (EPI == 1) r = isShared ? m : tok[tokB + m];
        else          r = offE + m;
        rowIdx[tid] = r;
    }
    __syncthreads();

    const __half* We = (isShared ? sW : eW + (size_t)e * N * K) + (size_t)nBase * K;
    const float* be = (isShared ? sBias : eBias + (size_t)e * N);
    const int nChunks = K >> 6;

    const int warpM = (wid >> 1) * 64;
    const int warpN = (wid & 1) * 64;
    const int arow  = ((lane >> 3) & 1) * 8 + (lane & 7);
    const int ahalf = lane >> 4;
    const int brow  = (lane & 7) + ((lane >> 4) & 1) * 8;
    const int bhalf = (lane >> 3) & 1;

    float acc[4][8][4];
    #pragma unroll
    for (int i = 0; i < 4; i++)
        #pragma unroll
        for (int j = 0; j < 8; j++)
            #pragma unroll
            for (int q = 0; q < 4; q++) acc[i][j][q] = 0.f;

    auto load_chunk = [&](int chunk, int stage) {
        const int k0 = chunk * BKb;
        const unsigned st = sb + SM_OFF + stage * STB;
        #pragma unroll
        for (int i = 0; i < 8; i++) {             // A planes: 1024 x 16B each
            int idx = tid + i * NTHR;
            int r = idx >> 3, c = idx & 7;
            unsigned o = swz(r, c);
            size_t aoff = (size_t)rowIdx[r] * K + k0 + c * 8;
            CP16(st + o, Ah + aoff);
            if (EPI == 1) CP16(st + OP_T + o, Al + aoff);
        }
        #pragma unroll
        for (int i = 0; i < 8; i++) {             // B: 1024 x 16B
            int idx = tid + i * NTHR;
            int r = idx >> 3, c = idx & 7;
            unsigned o = swz(r, c);
            size_t boff = (size_t)r * K + k0 + c * 8;
            CP16(st + APL * OP_T + o, We + boff);
        }
    };

    auto compute = [&](int stage) {
        const unsigned st = sb + SM_OFF + stage * STB;
        #pragma unroll
        for (int ks = 0; ks < 4; ks++) {
            unsigned ah[4][4], bh[4][4];
            #pragma unroll
            for (int mf = 0; mf < 4; mf++) {
                int R = warpM + mf * 16 + arow;
                unsigned o = swz(R, ks * 2 + ahalf);
                LDSM4(ah[mf][0], ah[mf][1], ah[mf][2], ah[mf][3], st + o);
            }
            #pragma unroll
            for (int g = 0; g < 4; g++) {
                int Rn = warpN + g * 16 + brow;
                unsigned o = swz(Rn, ks * 2 + bhalf);
                LDSM4(bh[g][0], bh[g][1], bh[g][2], bh[g][3], st + APL * OP_T + o);
            }
            #pragma unroll
            for (int g = 0; g < 4; g++)
                #pragma unroll
                for (int mf = 0; mf < 4; mf++) {
                    MMAF16(acc[mf][2 * g],     ah[mf][0], ah[mf][1], ah[mf][2], ah[mf][3], bh[g][0], bh[g][1]);
                    MMAF16(acc[mf][2 * g + 1], ah[mf][0], ah[mf][1], ah[mf][2], ah[mf][3], bh[g][2], bh[g][3]);
                }
            if (EPI == 1) {
                unsigned al[4][4];
                #pragma unroll
                for (int mf = 0; mf < 4; mf++) {
                    int R = warpM + mf * 16 + arow;
                    unsigned o = swz(R, ks * 2 + ahalf);
                    LDSM4(al[mf][0], al[mf][1], al[mf][2], al[mf][3], st + OP_T + o);
                }
                #pragma unroll
                for (int g = 0; g < 4; g++)
                    #pragma unroll
                    for (int mf = 0; mf < 4; mf++) {
                        MMAF16(acc[mf][2 * g],     al[mf][0], al[mf][1], al[mf][2], al[mf][3], bh[g][0], bh[g][1]);
                        MMAF16(acc[mf][2 * g + 1], al[mf][0], al[mf][1], al[mf][2], al[mf][3], bh[g][2], bh[g][3]);
                    }
            }
        }
    };

    load_chunk(0, 0); CP_COMMIT();
    for (int i = 0; i < nChunks; i++) {
        CP_WAIT0();
        __syncthreads();
        if (i + 1 < nChunks) { load_chunk(i + 1, (i + 1) & 1); CP_COMMIT(); }
        compute(i & 1);
    }

    // ---------------- epilogue ----------------
    const int qr = lane >> 2, qc = (lane & 3) * 2;
    #pragma unroll
    for (int mf = 0; mf < 4; mf++) {
        #pragma unroll
        for (int h = 0; h < 2; h++) {
            const int m = mBase + warpM + mf * 16 + qr + h * 8;
            if (m >= M) continue;
            if (EPI == 2) {
                const int   tt = isShared ? m : tok[tokB + m];
                const float wv = isShared ? 1.f : wts[tokB + m];
                float* orow = Cf + (size_t)tt * N;
                #pragma unroll
                for (int nf = 0; nf < 8; nf++) {
                    const int n = nBase + warpN + nf * 8 + qc;
                    atomicAdd(orow + n,     wv * (acc[mf][nf][h * 2 + 0] + be[n]));
                    atomicAdd(orow + n + 1, wv * (acc[mf][nf][h * 2 + 1] + be[n + 1]));
                }
            } else {
                __half* hrow = Ch + (size_t)(offE + m) * N;
                __half* lrow = Cl + (size_t)(offE + m) * N;
                #pragma unroll
                for (int nf = 0; nf < 8; nf++) {
                    const int n = nBase + warpN + nf * 8 + qc;
                    float v0 = fmaxf(acc[mf][nf][h * 2 + 0] + be[n], 0.f);
                    float v1 = fmaxf(acc[mf][nf][h * 2 + 1] + be[n + 1], 0.f);
                    __half h0 = __float2half(v0), h1 = __float2half(v1);
                    float l0 = v0 - __half2float(h0), l1 = v1 - __half2float(h1);
                    *reinterpret_cast<unsigned*>(hrow + n) =
                        ((unsigned)__half_as_ushort(h1) << 16) | __half_as_ushort(h0);
                    *reinterpret_cast<unsigned*>(lrow + n) = pack2h(l0, l1);
                }
            }
        }
    }
}

// ---------------- host launcher ----------------
extern "C" void kernel_launch(void* const* d_in, const int* in_sizes, int n_in,
                              void* d_out, int out_size)
{
    const float* hs  = (const float*)d_in[0];
    const float* nw  = (const float*)d_in[1];
    const float* rw  = (const float*)d_in[2];
    const float* sw1 = (const float*)d_in[3];
    const float* sb1 = (const float*)d_in[4];
    const float* sw2 = (const float*)d_in[5];
    const float* sb2 = (const float*)d_in[6];
    const float* ew1 = (const float*)d_in[7];
    const float* eb1 = (const float*)d_in[8];
    const float* ew2 = (const float*)d_in[9];
    const float* eb2 = (const float*)d_in[10];
    float* out = (float*)d_out;

    const int SMEM1 = SM_OFF + 2 * (3 * OP_T);   // 99328 (EPI1: A-hi, A-lo, B)
    const int SMEM2 = SM_OFF + 2 * (2 * OP_T);   // 66560 (EPI2: A, B)

    static bool attr_done = false;
    if (!attr_done) {
        cudaFuncSetAttribute(mma_gemm<1>, cudaFuncAttributeMaxDynamicSharedMemorySize, SMEM1);
        cudaFuncSetAttribute(mma_gemm<2>, cudaFuncAttributeMaxDynamicSharedMemorySize, SMEM2);
        attr_done = true;
    }

    void *p;
    cudaGetSymbolAddress(&p, g_nh);   __half* nh  = (__half*)p;
    cudaGetSymbolAddress(&p, g_nl);   __half* nl  = (__half*)p;
    cudaGetSymbolAddress(&p, g_hh);   __half* hh  = (__half*)p;
    cudaGetSymbolAddress(&p, g_hl);   __half* hl  = (__half*)p;
    cudaGetSymbolAddress(&p, g_sw1h); __half* s1h = (__half*)p;
    cudaGetSymbolAddress(&p, g_sw2h); __half* s2h = (__half*)p;
    cudaGetSymbolAddress(&p, g_ew1h); __half* e1h = (__half*)p;
    cudaGetSymbolAddress(&p, g_ew2h); __half* e2h = (__half*)p;
    cudaGetSymbolAddress(&p, g_cnt);  int*   cnt  = (int*)p;
    cudaGetSymbolAddress(&p, g_tok);  int*   tokl = (int*)p;
    cudaGetSymbolAddress(&p, g_wt);   float* wtl  = (float*)p;

    const int gy = (Tt + BMt - 1) / BMt;   // 32

    // 1: sw1 convert (+ zero expert counters)
    splitT_kernel<<<dim3(Hh / 32, Dd / 32, 1), 256>>>(sw1, s1h, Dd, Hh, 1);
    // 2: ew1 convert
    splitT_kernel<<<dim3(Hh / 32, Dd / 32, Ee), 256>>>(ew1, e1h, Dd, Hh, 0);
    // 3: norm + router + scatter
    norm_router_kernel<<<Tt, 256>>>(hs, nw, rw);

    // 4: pooled L1 (experts gather + shared), 2-term A   <- ncu capture slot
    mma_gemm<1><<<dim3(Hh / BNt, gy, Ee + 1), NTHR, SMEM1>>>(
        nh, nl, e1h, s1h, eb1, sb1,
        nullptr, hh, hl, Hh, Dd, cnt, tokl, wtl);

    // 5: zero output
    zero_out_kernel<<<(Tt * Oo / 4) / 256, 256>>>((float4*)out);
    // 6-7: layer-2 weight converts
    splitT_kernel<<<dim3(Oo / 32, Hh / 32, 1), 256>>>(sw2, s2h, Hh, Oo, 0);
    splitT_kernel<<<dim3(Oo / 32, Hh / 32, Ee), 256>>>(ew2, e2h, Hh, Oo, 0);

    // 8: pooled L2 (scatter-atomic; shared weight 1.0), single-term A
    mma_gemm<2><<<dim3(Oo / BNt, gy, Ee + 1), NTHR, SMEM2>>>(
        hh, nullptr, e2h, s2h, eb2, sb2,
        out, nullptr, nullptr, Oo, Hh, cnt, tokl, wtl);
}

// round 15
// speedup vs baseline: 1.7827x; 1.2980x over previous
#include <cuda_runtime.h>
#include <cuda_fp16.h>

// ---------------- problem constants ----------------
#define Dd 1024
#define Hh 4096
#define Oo 1024
#define Ee 8
#define Tt 4096
#define A2 (2 * Tt)
#define HR (A2 + Tt)       // unified hidden rows: experts [0,A2), shared [A2, A2+Tt)

// GEMM tiling: CTA 128x128, 4 warps of 64x64, k-chunk 64 (128 B rows), 2 CTAs/SM
#define BMt 128
#define BNt 128
#define BKb 64
#define NTHR 128
#define OP_T 16384          // one operand plane: 128 rows * 128 B
#define STB  (2 * OP_T)     // stage: A + B
#define SM_OFF 1024
#define SMEM_TOT (SM_OFF + 2 * STB)   // 66560 -> 2 CTAs/SM

// ---------------- scratch ----------------
__device__ __half g_nh[(size_t)Tt * Dd];
__device__ __half g_hh[(size_t)HR * Hh];                            // unified hidden fp16
__device__ __half g_sw1h[(size_t)Hh * Dd];                          // [N=H, K=D] fp16
__device__ __half g_sw2h[(size_t)Oo * Hh];
__device__ __half g_ew1h[(size_t)Ee * Hh * Dd];
__device__ __half g_ew2h[(size_t)Ee * Oo * Hh];
__device__ int   g_cnt[Ee], g_tok[Ee * Tt];
__device__ float g_wt[Ee * Tt];

// ---------------- ptx helpers ----------------
__device__ __forceinline__ unsigned smem_u32(const void* p) {
    unsigned a;
    asm("{ .reg .u64 t; cvta.to.shared.u64 t, %1; cvt.u32.u64 %0, t; }" : "=r"(a) : "l"(p));
    return a;
}
#define CP16(dst, src) asm volatile("cp.async.cg.shared.global [%0], [%1], 16;" :: "r"(dst), "l"(src) : "memory")
#define CP_COMMIT() asm volatile("cp.async.commit_group;" ::: "memory")
#define CP_WAIT0()  asm volatile("cp.async.wait_group 0;" ::: "memory")

#define LDSM4(r0, r1, r2, r3, addr) \
    asm volatile("ldmatrix.sync.aligned.m8n8.x4.shared.b16 {%0,%1,%2,%3}, [%4];" \
        : "=r"(r0), "=r"(r1), "=r"(r2), "=r"(r3) : "r"(addr))

#define MMAF16(d, a0, a1, a2, a3, b0v, b1v) \
    asm volatile("mma.sync.aligned.m16n8k16.row.col.f32.f16.f16.f32 " \
        "{%0,%1,%2,%3}, {%4,%5,%6,%7}, {%8,%9}, {%0,%1,%2,%3};" \
        : "+f"((d)[0]), "+f"((d)[1]), "+f"((d)[2]), "+f"((d)[3]) \
        : "r"(a0), "r"(a1), "r"(a2), "r"(a3), "r"(b0v), "r"(b1v))

// swizzled byte offset within one operand tile (128 B rows, 8 x 16B chunks)
__device__ __forceinline__ unsigned swz(int row, int chunk) {
    return (unsigned)(row * 128 + ((chunk ^ (row & 7)) << 4));
}
__device__ __forceinline__ unsigned pack2h(float v0, float v1) {
    __half h0 = __float2half(v0), h1 = __float2half(v1);
    return ((unsigned)__half_as_ushort(h1) << 16) | __half_as_ushort(h0);
}

// ---------------- small kernels ----------------
__global__ void __launch_bounds__(256) zero_out_kernel(float4* out) {
    out[blockIdx.x * 256 + threadIdx.x] = make_float4(0.f, 0.f, 0.f, 0.f);
}

// weight transpose + fp16 convert: W[K,N] fp32 -> Wh[N,K] fp16 (optionally zero cnt)
__global__ void __launch_bounds__(256) splitT_kernel(
    const float* __restrict__ W, __half* __restrict__ hiT, int K, int N, int zeroCnt)
{
    if (zeroCnt && blockIdx.x == 0 && blockIdx.y == 0 && blockIdx.z == 0 && threadIdx.x < Ee)
        g_cnt[threadIdx.x] = 0;
    const int e = blockIdx.z;
    W   += (size_t)e * K * N;
    hiT += (size_t)e * N * K;
    __shared__ float tile[32][33];
    const int k0 = blockIdx.y * 32, n0 = blockIdx.x * 32;
    {
        const int tx = threadIdx.x & 31, ty = threadIdx.x >> 5;
        #pragma unroll
        for (int i = 0; i < 4; i++)
            tile[ty + 8 * i][tx] = W[(size_t)(k0 + ty + 8 * i) * N + n0 + tx];
    }
    __syncthreads();
    const int tx2 = threadIdx.x & 15;
    const int ty2 = threadIdx.x >> 4;
    #pragma unroll
    for (int i = 0; i < 2; i++) {
        const int nl = ty2 + 16 * i;
        const int kl = tx2 * 2;
        size_t o = (size_t)(n0 + nl) * K + k0 + kl;
        *reinterpret_cast<unsigned*>(hiT + o) = pack2h(tile[kl][nl], tile[kl + 1][nl]);
    }
}

// RMSNorm + router + top-2 scatter; emits fp16 normed activations
__global__ void __launch_bounds__(256) norm_router_kernel(
    const float* __restrict__ x, const float* __restrict__ nw, const float* __restrict__ rw)
{
    const int t = blockIdx.x;
    const float* xr = x + (size_t)t * Dd;
    __shared__ float sx[Dd];
    __shared__ float red[8];
    __shared__ float s_rstd;
    __shared__ float slog[Ee];

    float ss = 0.f;
    for (int d = threadIdx.x; d < Dd; d += 256) {
        float v = xr[d]; sx[d] = v; ss += v * v;
    }
    #pragma unroll
    for (int o = 16; o; o >>= 1) ss += __shfl_xor_sync(0xFFFFFFFFu, ss, o);
    if ((threadIdx.x & 31) == 0) red[threadIdx.x >> 5] = ss;
    __syncthreads();
    if (threadIdx.x == 0) {
        float s = 0.f;
        #pragma unroll
        for (int i = 0; i < 8; i++) s += red[i];
        s_rstd = rsqrtf(s / (float)Dd + 1e-8f);
    }
    __syncthreads();
    const float rstd = s_rstd;
    for (int d = threadIdx.x; d < Dd; d += 256) {
        float v = sx[d] * rstd * nw[d];
        sx[d] = v;
        g_nh[(size_t)t * Dd + d] = __float2half(v);
    }
    __syncthreads();

    const int w = threadIdx.x >> 5, lane = threadIdx.x & 31;
    if (w < Ee) {
        const float* rwr = rw + (size_t)w * Dd;
        float acc = 0.f;
        for (int d = lane; d < Dd; d += 32) acc += sx[d] * rwr[d];
        #pragma unroll
        for (int o = 16; o; o >>= 1) acc += __shfl_xor_sync(0xFFFFFFFFu, acc, o);
        if (lane == 0) slog[w] = acc;
    }
    __syncthreads();

    if (threadIdx.x == 0) {
        float p[Ee];
        #pragma unroll
        for (int e = 0; e < Ee; e++) p[e] = 1.f / (1.f + expf(-slog[e]));
        int i0 = 0;
        #pragma unroll
        for (int e = 1; e < Ee; e++) if (p[e] > p[i0]) i0 = e;
        int i1 = (i0 == 0) ? 1 : 0;
        #pragma unroll
        for (int e = 0; e < Ee; e++) { if (e == i0) continue; if (p[e] > p[i1]) i1 = e; }
        float s0 = p[i0], s1 = p[i1];
        float inv = 1.f / (s0 + s1 + 1e-6f);
        int a = atomicAdd(&g_cnt[i0], 1);
        g_tok[i0 * Tt + a] = t; g_wt[i0 * Tt + a] = s0 * inv;
        int b = atomicAdd(&g_cnt[i1], 1);
        g_tok[i1 * Tt + b] = t; g_wt[i1 * Tt + b] = s1 * inv;
    }
}

// ---------------- pooled HMMA fp16 GEMM (128x128 CTA, 4 warps, 2 CTAs/SM) ----------------
// Plain fp16 x fp16 -> fp32-accum, 1 MMA per tile-k.
// EPI 1: relu -> fp16 into unified hidden at row offE+m.
// EPI 2: atomicAdd(out[tgt], wv*(acc+bias)).
template<int EPI>
__global__ void __launch_bounds__(NTHR, 2) mma_gemm(
    const __half* __restrict__ Ah,
    const __half* __restrict__ eW, const __half* __restrict__ sW,
    const float* __restrict__ eBias, const float* __restrict__ sBias,
    float* __restrict__ Cf, __half* __restrict__ Ch,
    int N, int K,
    const int* __restrict__ cnts,
    const int* __restrict__ tok, const float* __restrict__ wts)
{
    const int e = blockIdx.z;
    const bool isShared = (e == Ee);

    extern __shared__ char smem[];
    int* rowIdx = (int*)smem;               // 128 ints at [0,512)
    int* sMeta  = (int*)(smem + 512);       // [0]=M, [1]=offE
    const unsigned sb = smem_u32(smem);
    const int tid = threadIdx.x, wid = tid >> 5, lane = tid & 31;

    if (tid == 0) {
        int run = 0;
        #pragma unroll
        for (int i = 0; i < Ee; i++) if (i < e) run += cnts[i];
        sMeta[1] = run;
        sMeta[0] = isShared ? Tt : cnts[e];
    }
    __syncthreads();
    const int M = sMeta[0], offE = sMeta[1];
    const int mBase = blockIdx.y * BMt;
    if (mBase >= M) return;
    const int nBase = blockIdx.x * BNt;
    const int tokB = e * Tt;

    if (tid < BMt) {
        int m = mBase + tid; if (m > M - 1) m = M - 1;
        int r;
        if (EPI == 1) r = isShared ? m : tok[tokB + m];
        else          r = offE + m;
        rowIdx[tid] = r;
    }
    __syncthreads();

    const __half* We = (isShared ? sW : eW + (size_t)e * N * K) + (size_t)nBase * K;
    const float* be = (isShared ? sBias : eBias + (size_t)e * N);
    const int nChunks = K >> 6;

    const int warpM = (wid >> 1) * 64;
    const int warpN = (wid & 1) * 64;
    const int arow  = ((lane >> 3) & 1) * 8 + (lane & 7);
    const int ahalf = lane >> 4;
    const int brow  = (lane & 7) + ((lane >> 4) & 1) * 8;
    const int bhalf = (lane >> 3) & 1;

    float acc[4][8][4];
    #pragma unroll
    for (int i = 0; i < 4; i++)
        #pragma unroll
        for (int j = 0; j < 8; j++)
            #pragma unroll
            for (int q = 0; q < 4; q++) acc[i][j][q] = 0.f;

    auto load_chunk = [&](int chunk, int stage) {
        const int k0 = chunk * BKb;
        const unsigned st = sb + SM_OFF + stage * STB;
        #pragma unroll
        for (int i = 0; i < 8; i++) {             // A: 1024 x 16B
            int idx = tid + i * NTHR;
            int r = idx >> 3, c = idx & 7;
            unsigned o = swz(r, c);
            size_t aoff = (size_t)rowIdx[r] * K + k0 + c * 8;
            CP16(st + o, Ah + aoff);
        }
        #pragma unroll
        for (int i = 0; i < 8; i++) {             // B: 1024 x 16B
            int idx = tid + i * NTHR;
            int r = idx >> 3, c = idx & 7;
            unsigned o = swz(r, c);
            size_t boff = (size_t)r * K + k0 + c * 8;
            CP16(st + OP_T + o, We + boff);
        }
    };

    auto compute = [&](int stage) {
        const unsigned st = sb + SM_OFF + stage * STB;
        #pragma unroll
        for (int ks = 0; ks < 4; ks++) {
            unsigned ah[4][4], bh[4][4];
            #pragma unroll
            for (int mf = 0; mf < 4; mf++) {
                int R = warpM + mf * 16 + arow;
                unsigned o = swz(R, ks * 2 + ahalf);
                LDSM4(ah[mf][0], ah[mf][1], ah[mf][2], ah[mf][3], st + o);
            }
            #pragma unroll
            for (int g = 0; g < 4; g++) {
                int Rn = warpN + g * 16 + brow;
                unsigned o = swz(Rn, ks * 2 + bhalf);
                LDSM4(bh[g][0], bh[g][1], bh[g][2], bh[g][3], st + OP_T + o);
            }
            #pragma unroll
            for (int g = 0; g < 4; g++)
                #pragma unroll
                for (int mf = 0; mf < 4; mf++) {
                    MMAF16(acc[mf][2 * g],     ah[mf][0], ah[mf][1], ah[mf][2], ah[mf][3], bh[g][0], bh[g][1]);
                    MMAF16(acc[mf][2 * g + 1], ah[mf][0], ah[mf][1], ah[mf][2], ah[mf][3], bh[g][2], bh[g][3]);
                }
        }
    };

    load_chunk(0, 0); CP_COMMIT();
    for (int i = 0; i < nChunks; i++) {
        CP_WAIT0();
        __syncthreads();
        if (i + 1 < nChunks) { load_chunk(i + 1, (i + 1) & 1); CP_COMMIT(); }
        compute(i & 1);
    }

    // ---------------- epilogue ----------------
    const int qr = lane >> 2, qc = (lane & 3) * 2;
    #pragma unroll
    for (int mf = 0; mf < 4; mf++) {
        #pragma unroll
        for (int h = 0; h < 2; h++) {
            const int m = mBase + warpM + mf * 16 + qr + h * 8;
            if (m >= M) continue;
            if (EPI == 2) {
                const int   tt = isShared ? m : tok[tokB + m];
                const float wv = isShared ? 1.f : wts[tokB + m];
                float* orow = Cf + (size_t)tt * N;
                #pragma unroll
                for (int nf = 0; nf < 8; nf++) {
                    const int n = nBase + warpN + nf * 8 + qc;
                    atomicAdd(orow + n,     wv * (acc[mf][nf][h * 2 + 0] + be[n]));
                    atomicAdd(orow + n + 1, wv * (acc[mf][nf][h * 2 + 1] + be[n + 1]));
                }
            } else {
                __half* hrow = Ch + (size_t)(offE + m) * N;
                #pragma unroll
                for (int nf = 0; nf < 8; nf++) {
                    const int n = nBase + warpN + nf * 8 + qc;
                    float v0 = fmaxf(acc[mf][nf][h * 2 + 0] + be[n], 0.f);
                    float v1 = fmaxf(acc[mf][nf][h * 2 + 1] + be[n + 1], 0.f);
                    *reinterpret_cast<unsigned*>(hrow + n) = pack2h(v0, v1);
                }
            }
        }
    }
}

// ---------------- host launcher ----------------
extern "C" void kernel_launch(void* const* d_in, const int* in_sizes, int n_in,
                              void* d_out, int out_size)
{
    const float* hs  = (const float*)d_in[0];
    const float* nw  = (const float*)d_in[1];
    const float* rw  = (const float*)d_in[2];
    const float* sw1 = (const float*)d_in[3];
    const float* sb1 = (const float*)d_in[4];
    const float* sw2 = (const float*)d_in[5];
    const float* sb2 = (const float*)d_in[6];
    const float* ew1 = (const float*)d_in[7];
    const float* eb1 = (const float*)d_in[8];
    const float* ew2 = (const float*)d_in[9];
    const float* eb2 = (const float*)d_in[10];
    float* out = (float*)d_out;

    static bool attr_done = false;
    if (!attr_done) {
        cudaFuncSetAttribute(mma_gemm<1>, cudaFuncAttributeMaxDynamicSharedMemorySize, SMEM_TOT);
        cudaFuncSetAttribute(mma_gemm<2>, cudaFuncAttributeMaxDynamicSharedMemorySize, SMEM_TOT);
        attr_done = true;
    }

    void *p;
    cudaGetSymbolAddress(&p, g_nh);   __half* nh  = (__half*)p;
    cudaGetSymbolAddress(&p, g_hh);   __half* hh  = (__half*)p;
    cudaGetSymbolAddress(&p, g_sw1h); __half* s1h = (__half*)p;
    cudaGetSymbolAddress(&p, g_sw2h); __half* s2h = (__half*)p;
    cudaGetSymbolAddress(&p, g_ew1h); __half* e1h = (__half*)p;
    cudaGetSymbolAddress(&p, g_ew2h); __half* e2h = (__half*)p;
    cudaGetSymbolAddress(&p, g_cnt);  int*   cnt  = (int*)p;
    cudaGetSymbolAddress(&p, g_tok);  int*   tokl = (int*)p;
    cudaGetSymbolAddress(&p, g_wt);   float* wtl  = (float*)p;

    const int gy = (Tt + BMt - 1) / BMt;   // 32

    // 1: sw1 convert (+ zero expert counters)
    splitT_kernel<<<dim3(Hh / 32, Dd / 32, 1), 256>>>(sw1, s1h, Dd, Hh, 1);
    // 2: ew1 convert
    splitT_kernel<<<dim3(Hh / 32, Dd / 32, Ee), 256>>>(ew1, e1h, Dd, Hh, 0);
    // 3: norm + router + scatter
    norm_router_kernel<<<Tt, 256>>>(hs, nw, rw);

    // 4: pooled L1 (experts gather + shared)   <- ncu capture slot
    mma_gemm<1><<<dim3(Hh / BNt, gy, Ee + 1), NTHR, SMEM_TOT>>>(
        nh, e1h, s1h, eb1, sb1,
        nullptr, hh, Hh, Dd, cnt, tokl, wtl);

    // 5: zero output
    zero_out_kernel<<<(Tt * Oo / 4) / 256, 256>>>((float4*)out);
    // 6-7: layer-2 weight converts
    splitT_kernel<<<dim3(Oo / 32, Hh / 32, 1), 256>>>(sw2, s2h, Hh, Oo, 0);
    splitT_kernel<<<dim3(Oo / 32, Hh / 32, Ee), 256>>>(ew2, e2h, Hh, Oo, 0);

    // 8: pooled L2 (scatter-atomic; shared weight 1.0)
    mma_gemm<2><<<dim3(Oo / BNt, gy, Ee + 1), NTHR, SMEM_TOT>>>(
        hh, e2h, s2h, eb2, sb2,
        out, nullptr, Oo, Hh, cnt, tokl, wtl);
}

// round 16
// speedup vs baseline: 1.8338x; 1.0287x over previous
#include <cuda_runtime.h>
#include <cuda_fp16.h>

// ---------------- problem constants ----------------
#define Dd 1024
#define Hh 4096
#define Oo 1024
#define Ee 8
#define Tt 4096
#define A2 (2 * Tt)
#define HR (A2 + Tt)       // unified hidden rows: experts [0,A2), shared [A2, A2+Tt)

// GEMM tiling: CTA 128x128, 4 warps of 64x64, k-chunk 64 (128 B rows), 3-stage, 2 CTAs/SM
#define BMt 128
#define BNt 128
#define BKb 64
#define NTHR 128
#define OP_T 16384          // one operand plane: 128 rows * 128 B
#define STB  (2 * OP_T)     // stage: A + B = 32 KB
#define SM_OFF 1024
#define SMEM_TOT (SM_OFF + 3 * STB)   // 99328 -> 2 CTAs/SM

// ---------------- scratch ----------------
__device__ __half g_nh[(size_t)Tt * Dd];
__device__ __half g_hh[(size_t)HR * Hh];                            // unified hidden fp16
__device__ __half g_sw1h[(size_t)Hh * Dd];                          // [N=H, K=D] fp16
__device__ __half g_sw2h[(size_t)Oo * Hh];
__device__ __half g_ew1h[(size_t)Ee * Hh * Dd];
__device__ __half g_ew2h[(size_t)Ee * Oo * Hh];
__device__ int   g_cnt[Ee], g_tok[Ee * Tt];
__device__ float g_wt[Ee * Tt];

// ---------------- ptx helpers ----------------
__device__ __forceinline__ unsigned smem_u32(const void* p) {
    unsigned a;
    asm("{ .reg .u64 t; cvta.to.shared.u64 t, %1; cvt.u32.u64 %0, t; }" : "=r"(a) : "l"(p));
    return a;
}
#define CP16(dst, src) asm volatile("cp.async.cg.shared.global [%0], [%1], 16;" :: "r"(dst), "l"(src) : "memory")
#define CP_COMMIT() asm volatile("cp.async.commit_group;" ::: "memory")
#define CP_WAIT1()  asm volatile("cp.async.wait_group 1;" ::: "memory")

#define LDSM4(r0, r1, r2, r3, addr) \
    asm volatile("ldmatrix.sync.aligned.m8n8.x4.shared.b16 {%0,%1,%2,%3}, [%4];" \
        : "=r"(r0), "=r"(r1), "=r"(r2), "=r"(r3) : "r"(addr))

#define MMAF16(d, a0, a1, a2, a3, b0v, b1v) \
    asm volatile("mma.sync.aligned.m16n8k16.row.col.f32.f16.f16.f32 " \
        "{%0,%1,%2,%3}, {%4,%5,%6,%7}, {%8,%9}, {%0,%1,%2,%3};" \
        : "+f"((d)[0]), "+f"((d)[1]), "+f"((d)[2]), "+f"((d)[3]) \
        : "r"(a0), "r"(a1), "r"(a2), "r"(a3), "r"(b0v), "r"(b1v))

// swizzled byte offset within one operand tile (128 B rows, 8 x 16B chunks)
__device__ __forceinline__ unsigned swz(int row, int chunk) {
    return (unsigned)(row * 128 + ((chunk ^ (row & 7)) << 4));
}
__device__ __forceinline__ unsigned pack2h(float v0, float v1) {
    __half h0 = __float2half(v0), h1 = __float2half(v1);
    return ((unsigned)__half_as_ushort(h1) << 16) | __half_as_ushort(h0);
}

// ---------------- small kernels ----------------
__global__ void __launch_bounds__(256) zero_out_kernel(float4* out) {
    out[blockIdx.x * 256 + threadIdx.x] = make_float4(0.f, 0.f, 0.f, 0.f);
}

// weight transpose + fp16 convert: W[K,N] fp32 -> Wh[N,K] fp16.
// 64x64 tiles; float2 coalesced reads; warp-coherent 128B contiguous writes.
__global__ void __launch_bounds__(256) splitT_kernel(
    const float* __restrict__ W, __half* __restrict__ hiT, int K, int N, int zeroCnt)
{
    if (zeroCnt && blockIdx.x == 0 && blockIdx.y == 0 && blockIdx.z == 0 && threadIdx.x < Ee)
        g_cnt[threadIdx.x] = 0;
    const int e = blockIdx.z;
    W   += (size_t)e * K * N;
    hiT += (size_t)e * N * K;
    __shared__ float tile[64][65];
    const int k0 = blockIdx.y * 64, n0 = blockIdx.x * 64;
    {
        const int c  = (threadIdx.x & 31) * 2;
        const int r0 = threadIdx.x >> 5;
        #pragma unroll
        for (int i = 0; i < 8; i++) {
            const int r = r0 + i * 8;
            float2 v = *reinterpret_cast<const float2*>(W + (size_t)(k0 + r) * N + n0 + c);
            tile[r][c] = v.x; tile[r][c + 1] = v.y;
        }
    }
    __syncthreads();
    {
        const int lane = threadIdx.x & 31, w = threadIdx.x >> 5;
        const int kl = lane * 2;
        #pragma unroll
        for (int i = 0; i < 8; i++) {
            const int nl = w + i * 8;
            *reinterpret_cast<unsigned*>(hiT + (size_t)(n0 + nl) * K + k0 + kl) =
                pack2h(tile[kl][nl], tile[kl + 1][nl]);
        }
    }
}

// RMSNorm + router + top-2 scatter; emits fp16 normed activations
__global__ void __launch_bounds__(256) norm_router_kernel(
    const float* __restrict__ x, const float* __restrict__ nw, const float* __restrict__ rw)
{
    const int t = blockIdx.x;
    const float* xr = x + (size_t)t * Dd;
    __shared__ float sx[Dd];
    __shared__ float red[8];
    __shared__ float s_rstd;
    __shared__ float slog[Ee];

    float ss = 0.f;
    for (int d = threadIdx.x; d < Dd; d += 256) {
        float v = xr[d]; sx[d] = v; ss += v * v;
    }
    #pragma unroll
    for (int o = 16; o; o >>= 1) ss += __shfl_xor_sync(0xFFFFFFFFu, ss, o);
    if ((threadIdx.x & 31) == 0) red[threadIdx.x >> 5] = ss;
    __syncthreads();
    if (threadIdx.x == 0) {
        float s = 0.f;
        #pragma unroll
        for (int i = 0; i < 8; i++) s += red[i];
        s_rstd = rsqrtf(s / (float)Dd + 1e-8f);
    }
    __syncthreads();
    const float rstd = s_rstd;
    for (int d = threadIdx.x; d < Dd; d += 256) {
        float v = sx[d] * rstd * nw[d];
        sx[d] = v;
        g_nh[(size_t)t * Dd + d] = __float2half(v);
    }
    __syncthreads();

    const int w = threadIdx.x >> 5, lane = threadIdx.x & 31;
    if (w < Ee) {
        const float* rwr = rw + (size_t)w * Dd;
        float acc = 0.f;
        for (int d = lane; d < Dd; d += 32) acc += sx[d] * rwr[d];
        #pragma unroll
        for (int o = 16; o; o >>= 1) acc += __shfl_xor_sync(0xFFFFFFFFu, acc, o);
        if (lane == 0) slog[w] = acc;
    }
    __syncthreads();

    if (threadIdx.x == 0) {
        float p[Ee];
        #pragma unroll
        for (int e = 0; e < Ee; e++) p[e] = 1.f / (1.f + expf(-slog[e]));
        int i0 = 0;
        #pragma unroll
        for (int e = 1; e < Ee; e++) if (p[e] > p[i0]) i0 = e;
        int i1 = (i0 == 0) ? 1 : 0;
        #pragma unroll
        for (int e = 0; e < Ee; e++) { if (e == i0) continue; if (p[e] > p[i1]) i1 = e; }
        float s0 = p[i0], s1 = p[i1];
        float inv = 1.f / (s0 + s1 + 1e-6f);
        int a = atomicAdd(&g_cnt[i0], 1);
        g_tok[i0 * Tt + a] = t; g_wt[i0 * Tt + a] = s0 * inv;
        int b = atomicAdd(&g_cnt[i1], 1);
        g_tok[i1 * Tt + b] = t; g_wt[i1 * Tt + b] = s1 * inv;
    }
}

// ---------------- pooled HMMA fp16 GEMM (128x128 CTA, 4 warps, 3-stage, 2 CTAs/SM) ----------------
// Plain fp16 x fp16 -> fp32-accum, 1 MMA per tile-k.
// Pipeline: wait_group 1 -> sync -> issue load(i+2) -> compute(i): chunk i+1 stays
// in flight through compute(i).
// EPI 1: relu -> fp16 into unified hidden at row offE+m.
// EPI 2: atomicAdd(out[tgt], wv*(acc+bias)).
template<int EPI>
__global__ void __launch_bounds__(NTHR, 2) mma_gemm(
    const __half* __restrict__ Ah,
    const __half* __restrict__ eW, const __half* __restrict__ sW,
    const float* __restrict__ eBias, const float* __restrict__ sBias,
    float* __restrict__ Cf, __half* __restrict__ Ch,
    int N, int K,
    const int* __restrict__ cnts,
    const int* __restrict__ tok, const float* __restrict__ wts)
{
    const int e = blockIdx.z;
    const bool isShared = (e == Ee);

    extern __shared__ char smem[];
    int* rowIdx = (int*)smem;               // 128 ints at [0,512)
    int* sMeta  = (int*)(smem + 512);       // [0]=M, [1]=offE
    const unsigned sb = smem_u32(smem);
    const int tid = threadIdx.x, wid = tid >> 5, lane = tid & 31;

    if (tid == 0) {
        int run = 0;
        #pragma unroll
        for (int i = 0; i < Ee; i++) if (i < e) run += cnts[i];
        sMeta[1] = run;
        sMeta[0] = isShared ? Tt : cnts[e];
    }
    __syncthreads();
    const int M = sMeta[0], offE = sMeta[1];
    const int mBase = blockIdx.y * BMt;
    if (mBase >= M) return;
    const int nBase = blockIdx.x * BNt;
    const int tokB = e * Tt;

    if (tid < BMt) {
        int m = mBase + tid; if (m > M - 1) m = M - 1;
        int r;
        if (EPI == 1) r = isShared ? m : tok[tokB + m];
        else          r = offE + m;
        rowIdx[tid] = r;
    }
    __syncthreads();

    const __half* We = (isShared ? sW : eW + (size_t)e * N * K) + (size_t)nBase * K;
    const float* be = (isShared ? sBias : eBias + (size_t)e * N);
    const int nChunks = K >> 6;

    const int warpM = (wid >> 1) * 64;
    const int warpN = (wid & 1) * 64;
    const int arow  = ((lane >> 3) & 1) * 8 + (lane & 7);
    const int ahalf = lane >> 4;
    const int brow  = (lane & 7) + ((lane >> 4) & 1) * 8;
    const int bhalf = (lane >> 3) & 1;

    float acc[4][8][4];
    #pragma unroll
    for (int i = 0; i < 4; i++)
        #pragma unroll
        for (int j = 0; j < 8; j++)
            #pragma unroll
            for (int q = 0; q < 4; q++) acc[i][j][q] = 0.f;

    auto load_chunk = [&](int chunk, int stage) {
        const int k0 = chunk * BKb;
        const unsigned st = sb + SM_OFF + stage * STB;
        #pragma unroll
        for (int i = 0; i < 8; i++) {             // A: 1024 x 16B
            int idx = tid + i * NTHR;
            int r = idx >> 3, c = idx & 7;
            unsigned o = swz(r, c);
            size_t aoff = (size_t)rowIdx[r] * K + k0 + c * 8;
            CP16(st + o, Ah + aoff);
        }
        #pragma unroll
        for (int i = 0; i < 8; i++) {             // B: 1024 x 16B
            int idx = tid + i * NTHR;
            int r = idx >> 3, c = idx & 7;
            unsigned o = swz(r, c);
            size_t boff = (size_t)r * K + k0 + c * 8;
            CP16(st + OP_T + o, We + boff);
        }
    };

    auto compute = [&](int stage) {
        const unsigned st = sb + SM_OFF + stage * STB;
        #pragma unroll
        for (int ks = 0; ks < 4; ks++) {
            unsigned ah[4][4], bh[4][4];
            #pragma unroll
            for (int mf = 0; mf < 4; mf++) {
                int R = warpM + mf * 16 + arow;
                unsigned o = swz(R, ks * 2 + ahalf);
                LDSM4(ah[mf][0], ah[mf][1], ah[mf][2], ah[mf][3], st + o);
            }
            #pragma unroll
            for (int g = 0; g < 4; g++) {
                int Rn = warpN + g * 16 + brow;
                unsigned o = swz(Rn, ks * 2 + bhalf);
                LDSM4(bh[g][0], bh[g][1], bh[g][2], bh[g][3], st + OP_T + o);
            }
            #pragma unroll
            for (int g = 0; g < 4; g++)
                #pragma unroll
                for (int mf = 0; mf < 4; mf++) {
                    MMAF16(acc[mf][2 * g],     ah[mf][0], ah[mf][1], ah[mf][2], ah[mf][3], bh[g][0], bh[g][1]);
                    MMAF16(acc[mf][2 * g + 1], ah[mf][0], ah[mf][1], ah[mf][2], ah[mf][3], bh[g][2], bh[g][3]);
                }
        }
    };

    // 3-stage pipeline
    load_chunk(0, 0); CP_COMMIT();
    load_chunk(1, 1); CP_COMMIT();
    for (int i = 0; i < nChunks; i++) {
        CP_WAIT1();                     // chunk i landed; chunk i+1 may stay in flight
        __syncthreads();                // all warps done with stage (i+2)%3 (= compute(i-1))
        if (i + 2 < nChunks) load_chunk(i + 2, (i + 2) % 3);
        CP_COMMIT();                    // always commit (empty at tail keeps accounting)
        compute(i % 3);
    }

    // ---------------- epilogue ----------------
    const int qr = lane >> 2, qc = (lane & 3) * 2;
    #pragma unroll
    for (int mf = 0; mf < 4; mf++) {
        #pragma unroll
        for (int h = 0; h < 2; h++) {
            const int m = mBase + warpM + mf * 16 + qr + h * 8;
            if (m >= M) continue;
            if (EPI == 2) {
                const int   tt = isShared ? m : tok[tokB + m];
                const float wv = isShared ? 1.f : wts[tokB + m];
                float* orow = Cf + (size_t)tt * N;
                #pragma unroll
                for (int nf = 0; nf < 8; nf++) {
                    const int n = nBase + warpN + nf * 8 + qc;
                    atomicAdd(orow + n,     wv * (acc[mf][nf][h * 2 + 0] + be[n]));
                    atomicAdd(orow + n + 1, wv * (acc[mf][nf][h * 2 + 1] + be[n + 1]));
                }
            } else {
                __half* hrow = Ch + (size_t)(offE + m) * N;
                #pragma unroll
                for (int nf = 0; nf < 8; nf++) {
                    const int n = nBase + warpN + nf * 8 + qc;
                    float v0 = fmaxf(acc[mf][nf][h * 2 + 0] + be[n], 0.f);
                    float v1 = fmaxf(acc[mf][nf][h * 2 + 1] + be[n + 1], 0.f);
                    *reinterpret_cast<unsigned*>(hrow + n) = pack2h(v0, v1);
                }
            }
        }
    }
}

// ---------------- host launcher ----------------
extern "C" void kernel_launch(void* const* d_in, const int* in_sizes, int n_in,
                              void* d_out, int out_size)
{
    const float* hs  = (const float*)d_in[0];
    const float* nw  = (const float*)d_in[1];
    const float* rw  = (const float*)d_in[2];
    const float* sw1 = (const float*)d_in[3];
    const float* sb1 = (const float*)d_in[4];
    const float* sw2 = (const float*)d_in[5];
    const float* sb2 = (const float*)d_in[6];
    const float* ew1 = (const float*)d_in[7];
    const float* eb1 = (const float*)d_in[8];
    const float* ew2 = (const float*)d_in[9];
    const float* eb2 = (const float*)d_in[10];
    float* out = (float*)d_out;

    static bool attr_done = false;
    if (!attr_done) {
        cudaFuncSetAttribute(mma_gemm<1>, cudaFuncAttributeMaxDynamicSharedMemorySize, SMEM_TOT);
        cudaFuncSetAttribute(mma_gemm<2>, cudaFuncAttributeMaxDynamicSharedMemorySize, SMEM_TOT);
        attr_done = true;
    }

    void *p;
    cudaGetSymbolAddress(&p, g_nh);   __half* nh  = (__half*)p;
    cudaGetSymbolAddress(&p, g_hh);   __half* hh  = (__half*)p;
    cudaGetSymbolAddress(&p, g_sw1h); __half* s1h = (__half*)p;
    cudaGetSymbolAddress(&p, g_sw2h); __half* s2h = (__half*)p;
    cudaGetSymbolAddress(&p, g_ew1h); __half* e1h = (__half*)p;
    cudaGetSymbolAddress(&p, g_ew2h); __half* e2h = (__half*)p;
    cudaGetSymbolAddress(&p, g_cnt);  int*   cnt  = (int*)p;
    cudaGetSymbolAddress(&p, g_tok);  int*   tokl = (int*)p;
    cudaGetSymbolAddress(&p, g_wt);   float* wtl  = (float*)p;

    const int gy = (Tt + BMt - 1) / BMt;   // 32

    // 1: sw1 convert (+ zero expert counters)
    splitT_kernel<<<dim3(Hh / 64, Dd / 64, 1), 256>>>(sw1, s1h, Dd, Hh, 1);
    // 2: ew1 convert
    splitT_kernel<<<dim3(Hh / 64, Dd / 64, Ee), 256>>>(ew1, e1h, Dd, Hh, 0);
    // 3: norm + router + scatter
    norm_router_kernel<<<Tt, 256>>>(hs, nw, rw);

    // 4: pooled L1 (experts gather + shared)   <- ncu capture slot
    mma_gemm<1><<<dim3(Hh / BNt, gy, Ee + 1), NTHR, SMEM_TOT>>>(
        nh, e1h, s1h, eb1, sb1,
        nullptr, hh, Hh, Dd, cnt, tokl, wtl);

    // 5: zero output
    zero_out_kernel<<<(Tt * Oo / 4) / 256, 256>>>((float4*)out);
    // 6-7: layer-2 weight converts
    splitT_kernel<<<dim3(Oo / 64, Hh / 64, 1), 256>>>(sw2, s2h, Hh, Oo, 0);
    splitT_kernel<<<dim3(Oo / 64, Hh / 64, Ee), 256>>>(ew2, e2h, Hh, Oo, 0);

    // 8: pooled L2 (scatter-atomic; shared weight 1.0)
    mma_gemm<2><<<dim3(Oo / BNt, gy, Ee + 1), NTHR, SMEM_TOT>>>(
        hh, e2h, s2h, eb2, sb2,
        out, nullptr, Oo, Hh, cnt, tokl, wtl);
}

// round 17
// speedup vs baseline: 1.8938x; 1.0327x over previous
#include <cuda_runtime.h>
#include <cuda_fp16.h>

// ---------------- problem constants ----------------
#define Dd 1024
#define Hh 4096
#define Oo 1024
#define Ee 8
#define Tt 4096
#define A2 (2 * Tt)
#define HR (A2 + Tt)       // unified hidden rows: experts [0,A2), shared [A2, A2+Tt)

// GEMM tiling: CTA 128x128, 4 warps of 64x64, k-chunk 64 (128 B rows), 3-stage, 2 CTAs/SM
#define BMt 128
#define BNt 128
#define BKb 64
#define NTHR 128
#define OP_T 16384          // one operand plane: 128 rows * 128 B
#define STB  (2 * OP_T)     // stage: A + B = 32 KB
#define SM_OFF 1024
#define SMEM_TOT (SM_OFF + 3 * STB)   // 99328 -> 2 CTAs/SM

// ---------------- scratch ----------------
__device__ __half g_nh[(size_t)Tt * Dd];
__device__ __half g_hh[(size_t)HR * Hh];                            // unified hidden fp16
__device__ __half g_sw1h[(size_t)Hh * Dd];                          // [N=H, K=D] fp16
__device__ __half g_sw2h[(size_t)Oo * Hh];
__device__ __half g_ew1h[(size_t)Ee * Hh * Dd];
__device__ __half g_ew2h[(size_t)Ee * Oo * Hh];
__device__ int   g_cnt[Ee], g_tok[Ee * Tt];
__device__ float g_wt[Ee * Tt];

// ---------------- ptx helpers ----------------
__device__ __forceinline__ unsigned smem_u32(const void* p) {
    unsigned a;
    asm("{ .reg .u64 t; cvta.to.shared.u64 t, %1; cvt.u32.u64 %0, t; }" : "=r"(a) : "l"(p));
    return a;
}
#define CP16(dst, src) asm volatile("cp.async.cg.shared.global [%0], [%1], 16;" :: "r"(dst), "l"(src) : "memory")
#define CP_COMMIT() asm volatile("cp.async.commit_group;" ::: "memory")
#define CP_WAIT1()  asm volatile("cp.async.wait_group 1;" ::: "memory")

#define LDSM4(r0, r1, r2, r3, addr) \
    asm volatile("ldmatrix.sync.aligned.m8n8.x4.shared.b16 {%0,%1,%2,%3}, [%4];" \
        : "=r"(r0), "=r"(r1), "=r"(r2), "=r"(r3) : "r"(addr))

#define MMAF16(d, a0, a1, a2, a3, b0v, b1v) \
    asm volatile("mma.sync.aligned.m16n8k16.row.col.f32.f16.f16.f32 " \
        "{%0,%1,%2,%3}, {%4,%5,%6,%7}, {%8,%9}, {%0,%1,%2,%3};" \
        : "+f"((d)[0]), "+f"((d)[1]), "+f"((d)[2]), "+f"((d)[3]) \
        : "r"(a0), "r"(a1), "r"(a2), "r"(a3), "r"(b0v), "r"(b1v))

// swizzled byte offset within one operand tile (128 B rows, 8 x 16B chunks)
__device__ __forceinline__ unsigned swz(int row, int chunk) {
    return (unsigned)(row * 128 + ((chunk ^ (row & 7)) << 4));
}
__device__ __forceinline__ unsigned pack2h(float v0, float v1) {
    __half h0 = __float2half(v0), h1 = __float2half(v1);
    return ((unsigned)__half_as_ushort(h1) << 16) | __half_as_ushort(h0);
}

// ---------------- small kernels ----------------
__global__ void zero_cnt_kernel() {
    if (threadIdx.x < Ee) g_cnt[threadIdx.x] = 0;
}
__global__ void __launch_bounds__(256) zero_out_kernel(float4* out) {
    out[blockIdx.x * 256 + threadIdx.x] = make_float4(0.f, 0.f, 0.f, 0.f);
}

// pooled weight transpose + fp16 convert: z<Ee -> expert weights, z==Ee -> shared.
// W[K,N] fp32 -> Wh[N,K] fp16. 64x64 tiles; float2 reads; 128B contiguous writes.
__global__ void __launch_bounds__(256) splitT_kernel(
    const float* __restrict__ eW, const float* __restrict__ sW,
    __half* __restrict__ eOut, __half* __restrict__ sOut, int K, int N)
{
    const int e = blockIdx.z;
    const bool isShared = (e == Ee);
    const float* W = isShared ? sW : eW + (size_t)e * K * N;
    __half* hiT    = isShared ? sOut : eOut + (size_t)e * N * K;
    __shared__ float tile[64][65];
    const int k0 = blockIdx.y * 64, n0 = blockIdx.x * 64;
    {
        const int c  = (threadIdx.x & 31) * 2;
        const int r0 = threadIdx.x >> 5;
        #pragma unroll
        for (int i = 0; i < 8; i++) {
            const int r = r0 + i * 8;
            float2 v = *reinterpret_cast<const float2*>(W + (size_t)(k0 + r) * N + n0 + c);
            tile[r][c] = v.x; tile[r][c + 1] = v.y;
        }
    }
    __syncthreads();
    {
        const int lane = threadIdx.x & 31, w = threadIdx.x >> 5;
        const int kl = lane * 2;
        #pragma unroll
        for (int i = 0; i < 8; i++) {
            const int nl = w + i * 8;
            *reinterpret_cast<unsigned*>(hiT + (size_t)(n0 + nl) * K + k0 + kl) =
                pack2h(tile[kl][nl], tile[kl + 1][nl]);
        }
    }
}

// RMSNorm + router + top-2 scatter; emits fp16 normed activations
__global__ void __launch_bounds__(256) norm_router_kernel(
    const float* __restrict__ x, const float* __restrict__ nw, const float* __restrict__ rw)
{
    const int t = blockIdx.x;
    const float* xr = x + (size_t)t * Dd;
    __shared__ float sx[Dd];
    __shared__ float red[8];
    __shared__ float s_rstd;
    __shared__ float slog[Ee];

    float ss = 0.f;
    for (int d = threadIdx.x; d < Dd; d += 256) {
        float v = xr[d]; sx[d] = v; ss += v * v;
    }
    #pragma unroll
    for (int o = 16; o; o >>= 1) ss += __shfl_xor_sync(0xFFFFFFFFu, ss, o);
    if ((threadIdx.x & 31) == 0) red[threadIdx.x >> 5] = ss;
    __syncthreads();
    if (threadIdx.x == 0) {
        float s = 0.f;
        #pragma unroll
        for (int i = 0; i < 8; i++) s += red[i];
        s_rstd = rsqrtf(s / (float)Dd + 1e-8f);
    }
    __syncthreads();
    const float rstd = s_rstd;
    for (int d = threadIdx.x; d < Dd; d += 256) {
        float v = sx[d] * rstd * nw[d];
        sx[d] = v;
        g_nh[(size_t)t * Dd + d] = __float2half(v);
    }
    __syncthreads();

    const int w = threadIdx.x >> 5, lane = threadIdx.x & 31;
    if (w < Ee) {
        const float* rwr = rw + (size_t)w * Dd;
        float acc = 0.f;
        for (int d = lane; d < Dd; d += 32) acc += sx[d] * rwr[d];
        #pragma unroll
        for (int o = 16; o; o >>= 1) acc += __shfl_xor_sync(0xFFFFFFFFu, acc, o);
        if (lane == 0) slog[w] = acc;
    }
    __syncthreads();

    if (threadIdx.x == 0) {
        float p[Ee];
        #pragma unroll
        for (int e = 0; e < Ee; e++) p[e] = 1.f / (1.f + expf(-slog[e]));
        int i0 = 0;
        #pragma unroll
        for (int e = 1; e < Ee; e++) if (p[e] > p[i0]) i0 = e;
        int i1 = (i0 == 0) ? 1 : 0;
        #pragma unroll
        for (int e = 0; e < Ee; e++) { if (e == i0) continue; if (p[e] > p[i1]) i1 = e; }
        float s0 = p[i0], s1 = p[i1];
        float inv = 1.f / (s0 + s1 + 1e-6f);
        int a = atomicAdd(&g_cnt[i0], 1);
        g_tok[i0 * Tt + a] = t; g_wt[i0 * Tt + a] = s0 * inv;
        int b = atomicAdd(&g_cnt[i1], 1);
        g_tok[i1 * Tt + b] = t; g_wt[i1 * Tt + b] = s1 * inv;
    }
}

// ---------------- pooled HMMA fp16 GEMM (128x128 CTA, 4 warps, 3-stage, 2 CTAs/SM) ----------------
template<int EPI>
__global__ void __launch_bounds__(NTHR, 2) mma_gemm(
    const __half* __restrict__ Ah,
    const __half* __restrict__ eW, const __half* __restrict__ sW,
    const float* __restrict__ eBias, const float* __restrict__ sBias,
    float* __restrict__ Cf, __half* __restrict__ Ch,
    int N, int K,
    const int* __restrict__ cnts,
    const int* __restrict__ tok, const float* __restrict__ wts)
{
    const int e = blockIdx.z;
    const bool isShared = (e == Ee);

    extern __shared__ char smem[];
    int* rowIdx = (int*)smem;               // 128 ints at [0,512)
    int* sMeta  = (int*)(smem + 512);       // [0]=M, [1]=offE
    const unsigned sb = smem_u32(smem);
    const int tid = threadIdx.x, wid = tid >> 5, lane = tid & 31;

    if (tid == 0) {
        int run = 0;
        #pragma unroll
        for (int i = 0; i < Ee; i++) if (i < e) run += cnts[i];
        sMeta[1] = run;
        sMeta[0] = isShared ? Tt : cnts[e];
    }
    __syncthreads();
    const int M = sMeta[0], offE = sMeta[1];
    const int mBase = blockIdx.y * BMt;
    if (mBase >= M) return;
    const int nBase = blockIdx.x * BNt;
    const int tokB = e * Tt;

    if (tid < BMt) {
        int m = mBase + tid; if (m > M - 1) m = M - 1;
        int r;
        if (EPI == 1) r = isShared ? m : tok[tokB + m];
        else          r = offE + m;
        rowIdx[tid] = r;
    }
    __syncthreads();

    const __half* We = (isShared ? sW : eW + (size_t)e * N * K) + (size_t)nBase * K;
    const float* be = (isShared ? sBias : eBias + (size_t)e * N);
    const int nChunks = K >> 6;

    const int warpM = (wid >> 1) * 64;
    const int warpN = (wid & 1) * 64;
    const int arow  = ((lane >> 3) & 1) * 8 + (lane & 7);
    const int ahalf = lane >> 4;
    const int brow  = (lane & 7) + ((lane >> 4) & 1) * 8;
    const int bhalf = (lane >> 3) & 1;

    float acc[4][8][4];
    #pragma unroll
    for (int i = 0; i < 4; i++)
        #pragma unroll
        for (int j = 0; j < 8; j++)
            #pragma unroll
            for (int q = 0; q < 4; q++) acc[i][j][q] = 0.f;

    auto load_chunk = [&](int chunk, int stage) {
        const int k0 = chunk * BKb;
        const unsigned st = sb + SM_OFF + stage * STB;
        #pragma unroll
        for (int i = 0; i < 8; i++) {             // A: 1024 x 16B
            int idx = tid + i * NTHR;
            int r = idx >> 3, c = idx & 7;
            unsigned o = swz(r, c);
            size_t aoff = (size_t)rowIdx[r] * K + k0 + c * 8;
            CP16(st + o, Ah + aoff);
        }
        #pragma unroll
        for (int i = 0; i < 8; i++) {             // B: 1024 x 16B
            int idx = tid + i * NTHR;
            int r = idx >> 3, c = idx & 7;
            unsigned o = swz(r, c);
            size_t boff = (size_t)r * K + k0 + c * 8;
            CP16(st + OP_T + o, We + boff);
        }
    };

    auto compute = [&](int stage) {
        const unsigned st = sb + SM_OFF + stage * STB;
        #pragma unroll
        for (int ks = 0; ks < 4; ks++) {
            unsigned ah[4][4], bh[4][4];
            #pragma unroll
            for (int mf = 0; mf < 4; mf++) {
                int R = warpM + mf * 16 + arow;
                unsigned o = swz(R, ks * 2 + ahalf);
                LDSM4(ah[mf][0], ah[mf][1], ah[mf][2], ah[mf][3], st + o);
            }
            #pragma unroll
            for (int g = 0; g < 4; g++) {
                int Rn = warpN + g * 16 + brow;
                unsigned o = swz(Rn, ks * 2 + bhalf);
                LDSM4(bh[g][0], bh[g][1], bh[g][2], bh[g][3], st + OP_T + o);
            }
            #pragma unroll
            for (int g = 0; g < 4; g++)
                #pragma unroll
                for (int mf = 0; mf < 4; mf++) {
                    MMAF16(acc[mf][2 * g],     ah[mf][0], ah[mf][1], ah[mf][2], ah[mf][3], bh[g][0], bh[g][1]);
                    MMAF16(acc[mf][2 * g + 1], ah[mf][0], ah[mf][1], ah[mf][2], ah[mf][3], bh[g][2], bh[g][3]);
                }
        }
    };

    // 3-stage pipeline
    load_chunk(0, 0); CP_COMMIT();
    load_chunk(1, 1); CP_COMMIT();
    for (int i = 0; i < nChunks; i++) {
        CP_WAIT1();
        __syncthreads();
        if (i + 2 < nChunks) load_chunk(i + 2, (i + 2) % 3);
        CP_COMMIT();
        compute(i % 3);
    }

    // ---------------- epilogue ----------------
    const int qr = lane >> 2, qc = (lane & 3) * 2;
    #pragma unroll
    for (int mf = 0; mf < 4; mf++) {
        #pragma unroll
        for (int h = 0; h < 2; h++) {
            const int m = mBase + warpM + mf * 16 + qr + h * 8;
            if (m >= M) continue;
            if (EPI == 2) {
                const int   tt = isShared ? m : tok[tokB + m];
                const float wv = isShared ? 1.f : wts[tokB + m];
                float* orow = Cf + (size_t)tt * N;
                #pragma unroll
                for (int nf = 0; nf < 8; nf++) {
                    const int n = nBase + warpN + nf * 8 + qc;
                    atomicAdd(orow + n,     wv * (acc[mf][nf][h * 2 + 0] + be[n]));
                    atomicAdd(orow + n + 1, wv * (acc[mf][nf][h * 2 + 1] + be[n + 1]));
                }
            } else {
                __half* hrow = Ch + (size_t)(offE + m) * N;
                #pragma unroll
                for (int nf = 0; nf < 8; nf++) {
                    const int n = nBase + warpN + nf * 8 + qc;
                    float v0 = fmaxf(acc[mf][nf][h * 2 + 0] + be[n], 0.f);
                    float v1 = fmaxf(acc[mf][nf][h * 2 + 1] + be[n + 1], 0.f);
                    *reinterpret_cast<unsigned*>(hrow + n) = pack2h(v0, v1);
                }
            }
        }
    }
}

// ---------------- host launcher ----------------
extern "C" void kernel_launch(void* const* d_in, const int* in_sizes, int n_in,
                              void* d_out, int out_size)
{
    const float* hs  = (const float*)d_in[0];
    const float* nw  = (const float*)d_in[1];
    const float* rw  = (const float*)d_in[2];
    const float* sw1 = (const float*)d_in[3];
    const float* sb1 = (const float*)d_in[4];
    const float* sw2 = (const float*)d_in[5];
    const float* sb2 = (const float*)d_in[6];
    const float* ew1 = (const float*)d_in[7];
    const float* eb1 = (const float*)d_in[8];
    const float* ew2 = (const float*)d_in[9];
    const float* eb2 = (const float*)d_in[10];
    float* out = (float*)d_out;

    static cudaStream_t sSide = nullptr;
    static cudaEvent_t evFork = nullptr, evNorm = nullptr, evPrep = nullptr;
    if (!sSide) {
        cudaFuncSetAttribute(mma_gemm<1>, cudaFuncAttributeMaxDynamicSharedMemorySize, SMEM_TOT);
        cudaFuncSetAttribute(mma_gemm<2>, cudaFuncAttributeMaxDynamicSharedMemorySize, SMEM_TOT);
        cudaStreamCreateWithFlags(&sSide, cudaStreamNonBlocking);
        cudaEventCreateWithFlags(&evFork, cudaEventDisableTiming);
        cudaEventCreateWithFlags(&evNorm, cudaEventDisableTiming);
        cudaEventCreateWithFlags(&evPrep, cudaEventDisableTiming);
    }

    void *p;
    cudaGetSymbolAddress(&p, g_nh);   __half* nh  = (__half*)p;
    cudaGetSymbolAddress(&p, g_hh);   __half* hh  = (__half*)p;
    cudaGetSymbolAddress(&p, g_sw1h); __half* s1h = (__half*)p;
    cudaGetSymbolAddress(&p, g_sw2h); __half* s2h = (__half*)p;
    cudaGetSymbolAddress(&p, g_ew1h); __half* e1h = (__half*)p;
    cudaGetSymbolAddress(&p, g_ew2h); __half* e2h = (__half*)p;
    cudaGetSymbolAddress(&p, g_cnt);  int*   cnt  = (int*)p;
    cudaGetSymbolAddress(&p, g_tok);  int*   tokl = (int*)p;
    cudaGetSymbolAddress(&p, g_wt);   float* wtl  = (float*)p;

    const int gy = (Tt + BMt - 1) / BMt;   // 32

    // fork: side stream does norm + L2 prep, main does L1 weight prep + GEMMs
    cudaEventRecord(evFork, 0);
    cudaStreamWaitEvent(sSide, evFork, 0);

    // side: zero cnt -> norm/router -> [evNorm] -> L2 weight convert -> zero out -> [evPrep]
    zero_cnt_kernel<<<1, 32, 0, sSide>>>();
    norm_router_kernel<<<Tt, 256, 0, sSide>>>(hs, nw, rw);
    cudaEventRecord(evNorm, sSide);
    splitT_kernel<<<dim3(Oo / 64, Hh / 64, Ee + 1), 256, 0, sSide>>>(
        ew2, sw2, e2h, s2h, Hh, Oo);
    zero_out_kernel<<<(Tt * Oo / 4) / 256, 256, 0, sSide>>>((float4*)out);
    cudaEventRecord(evPrep, sSide);

    // main: L1 weight convert (pooled experts + shared)
    splitT_kernel<<<dim3(Hh / 64, Dd / 64, Ee + 1), 256>>>(
        ew1, sw1, e1h, s1h, Dd, Hh);
    cudaStreamWaitEvent(0, evNorm, 0);

    // main: pooled L1 GEMM (experts gather + shared)
    mma_gemm<1><<<dim3(Hh / BNt, gy, Ee + 1), NTHR, SMEM_TOT>>>(
        nh, e1h, s1h, eb1, sb1,
        nullptr, hh, Hh, Dd, cnt, tokl, wtl);

    cudaStreamWaitEvent(0, evPrep, 0);

    // main: pooled L2 GEMM (scatter-atomic; shared weight 1.0)
    mma_gemm<2><<<dim3(Oo / BNt, gy, Ee + 1), NTHR, SMEM_TOT>>>(
        hh, e2h, s2h, eb2, sb2,
        out, nullptr, Oo, Hh, cnt, tokl, wtl);
}